// round 4
// baseline (speedup 1.0000x reference)
#include <cuda_runtime.h>
#include <cuda_bf16.h>
#include <math.h>

#define BG   64
#define NPG  2048
#define EPG  32768
#define NTOT (BG * NPG)         // 131072
#define EDG  (BG * EPG)         // 2097152
#define K1   1639
#define NT1  (BG * K1)          // 104896 (= 64 * 1639, divisible by 64)
#define K2   1312
#define NT2  (BG * K2)          // 83968
#define DIM  64
#define NCLS 6
#define CAP  64                 // fixed CSR bucket capacity (P(deg>=64) ~ 1e-20)
#define FULLMASK 0xFFFFFFFFu

typedef unsigned long long ull;

// ---------------- scratch ----------------------------------------------------
__device__ float g_xw[NTOT * DIM];       // x@W (stage1), gathered-xp@W2 (stage2)
__device__ float g_h[NTOT * DIM];        // conv output (relu'd)
__device__ float g_score[NTOT];
__device__ float g_rdeg[NTOT];           // rsqrt(deg incl self-loop)
__device__ int   g_cnt[NTOT];            // in-degree (excl self-loop)
__device__ int   g_elist[NTOT * CAP];    // fixed-stride CSR: src per dst-slot
__device__ int   g_perm[NT1];
__device__ float g_vals[NT1];
__device__ int   g_newid[NTOT];
__device__ float g_x1[BG * 2 * DIM];
__device__ float g_x2[BG * 2 * DIM];

// ---------------- utility ----------------------------------------------------
__global__ void fill_i_kernel(int* p, int v, int n) {
    int t = blockIdx.x * blockDim.x + threadIdx.x;
    int stride = gridDim.x * blockDim.x;
    for (; t < n; t += stride) p[t] = v;
}

// fused count + place (stage 1: all edges valid)
__global__ void place1_kernel(const int* __restrict__ src, const int* __restrict__ dst,
                              int* __restrict__ cnt, int* __restrict__ elist, int nedges) {
    int t = blockIdx.x * blockDim.x + threadIdx.x;
    if (t >= nedges) return;
    int d = dst[t];
    int slot = atomicAdd(&cnt[d], 1);
    elist[d * CAP + slot] = src[t];
}

// fused remap + count + place (stage 2)
__global__ void place2_kernel(const int* __restrict__ src, const int* __restrict__ dst,
                              const int* __restrict__ newid,
                              int* __restrict__ cnt, int* __restrict__ elist, int nedges) {
    int t = blockIdx.x * blockDim.x + threadIdx.x;
    if (t >= nedges) return;
    int s2 = newid[src[t]];
    int d2 = newid[dst[t]];
    if (s2 < 0 || d2 < 0) return;
    int slot = atomicAdd(&cnt[d2], 1);
    elist[d2 * CAP + slot] = s2;
}

__global__ void rdeg_kernel(const int* __restrict__ cnt, float* __restrict__ rdeg, int n) {
    int i = blockIdx.x * blockDim.x + threadIdx.x;
    if (i < n) rdeg[i] = rsqrtf((float)(cnt[i] + 1));
}

// ---------------- packed f32x2 FMA (PTX-only; ptxas never auto-emits) --------
__device__ __forceinline__ void fma2(ull& d, ull a, ull b) {
    asm("fma.rn.f32x2 %0, %1, %2, %0;" : "+l"(d) : "l"(a), "l"(b));
}

// ---------------- GEMM: C[n x 64] = gather(A)[n x 64] @ W[64 x 64] ----------
// 64x64 tile per block (nrows % 64 == 0 guaranteed). Thread = 4 rows x 4 cols.
// A stored duplicated in smem (a,a pairs) so one LDS64 feeds an f32x2 broadcast;
// W row-major so one LDS128 yields two packed col-pairs.
// If perm != nullptr, row i of A is A[perm[i]] * vals[i] (fused TopK gather+gate).
__global__ __launch_bounds__(256) void matmul64_kernel(
    const float* __restrict__ A, const float* __restrict__ W,
    const int* __restrict__ perm, const float* __restrict__ vals,
    float* __restrict__ C, int nrows) {
    __shared__ float Ws[64][68];        // row k, cols j (row-major, padded)
    __shared__ float Ad[64][132];       // row r, duplicated k: [2k]=[2k+1]=a[r][k]
    int tid = threadIdx.x;
    // load W (4096 floats)
    for (int i = tid; i < 1024; i += 256) {
        int k = i >> 4, c4 = i & 15;
        float4 w = ((const float4*)W)[i];
        *(float4*)&Ws[k][c4 * 4] = w;
    }
    int row0 = blockIdx.x * 64;
    // load A rows (gather+gate if perm) and duplicate each scalar
    for (int i = tid; i < 1024; i += 256) {
        int r = i >> 4, c4 = i & 15;
        int grow = row0 + r;
        int arow = perm ? perm[grow] : grow;
        float sc = perm ? vals[grow] : 1.0f;
        float4 v = ((const float4*)(A + (size_t)arow * 64))[c4];
        v.x *= sc; v.y *= sc; v.z *= sc; v.w *= sc;
        *(float4*)&Ad[r][c4 * 8]     = make_float4(v.x, v.x, v.y, v.y);
        *(float4*)&Ad[r][c4 * 8 + 4] = make_float4(v.z, v.z, v.w, v.w);
    }
    __syncthreads();
    int tx = tid & 15;    // cols 4tx .. 4tx+3
    int ty = tid >> 4;    // rows 4ty .. 4ty+3
    ull acc[4][2] = {};
#pragma unroll 8
    for (int k = 0; k < 64; k++) {
        ulonglong2 w = *(const ulonglong2*)&Ws[k][tx * 4];
#pragma unroll
        for (int r = 0; r < 4; r++) {
            ull a = *(const ull*)&Ad[4 * ty + r][2 * k];
            fma2(acc[r][0], a, w.x);
            fma2(acc[r][1], a, w.y);
        }
    }
#pragma unroll
    for (int r = 0; r < 4; r++) {
        int row = row0 + 4 * ty + r;
        float2 lo = *(float2*)&acc[r][0];
        float2 hi = *(float2*)&acc[r][1];
        *(float4*)&C[(size_t)row * 64 + 4 * tx] = make_float4(lo.x, lo.y, hi.x, hi.y);
    }
}

// ---------------- fused CSR-gather conv + epilogue + score -------------------
// One warp per dst node; 4 quarter-warps each process alternate edges.
// Each lane covers 8 floats (2 float4) of the 64-float row.
__global__ __launch_bounds__(256) void conv_kernel(
    const int* __restrict__ cnt, const int* __restrict__ elist,
    const float* __restrict__ rdeg, const float* __restrict__ xw,
    const float* __restrict__ bias, const float* __restrict__ p,
    float* __restrict__ h, float* __restrict__ score, int n) {
    int warp = (blockIdx.x * blockDim.x + threadIdx.x) >> 5;
    int lane = threadIdx.x & 31;
    if (warp >= n) return;
    int qw = lane >> 3;   // 0..3: edge phase
    int li = lane & 7;    // float4-pair index within row
    const float4* xw4 = (const float4*)xw;
    float rd = rdeg[warp];
    int m = cnt[warp];
    const int* el = elist + (size_t)warp * CAP;
    float4 a0 = make_float4(0.f, 0.f, 0.f, 0.f);
    float4 a1 = make_float4(0.f, 0.f, 0.f, 0.f);
#pragma unroll 2
    for (int e = qw; e < m; e += 4) {
        int s = el[e];
        float nr = rdeg[s] * rd;
        float4 v0 = xw4[(size_t)s * 16 + 2 * li];
        float4 v1 = xw4[(size_t)s * 16 + 2 * li + 1];
        a0.x += nr * v0.x; a0.y += nr * v0.y; a0.z += nr * v0.z; a0.w += nr * v0.w;
        a1.x += nr * v1.x; a1.y += nr * v1.y; a1.z += nr * v1.z; a1.w += nr * v1.w;
    }
    // combine quarter-warps (all lanes end with full sums for their slice)
#pragma unroll
    for (int o = 8; o <= 16; o <<= 1) {
        a0.x += __shfl_xor_sync(FULLMASK, a0.x, o);
        a0.y += __shfl_xor_sync(FULLMASK, a0.y, o);
        a0.z += __shfl_xor_sync(FULLMASK, a0.z, o);
        a0.w += __shfl_xor_sync(FULLMASK, a0.w, o);
        a1.x += __shfl_xor_sync(FULLMASK, a1.x, o);
        a1.y += __shfl_xor_sync(FULLMASK, a1.y, o);
        a1.z += __shfl_xor_sync(FULLMASK, a1.z, o);
        a1.w += __shfl_xor_sync(FULLMASK, a1.w, o);
    }
    // self-loop (coef 1/deg = rd^2) + bias + relu
    float4 s0 = xw4[(size_t)warp * 16 + 2 * li];
    float4 s1 = xw4[(size_t)warp * 16 + 2 * li + 1];
    float4 b0 = ((const float4*)bias)[2 * li];
    float4 b1 = ((const float4*)bias)[2 * li + 1];
    float inv = rd * rd;
    a0.x = fmaxf(a0.x + s0.x * inv + b0.x, 0.f);
    a0.y = fmaxf(a0.y + s0.y * inv + b0.y, 0.f);
    a0.z = fmaxf(a0.z + s0.z * inv + b0.z, 0.f);
    a0.w = fmaxf(a0.w + s0.w * inv + b0.w, 0.f);
    a1.x = fmaxf(a1.x + s1.x * inv + b1.x, 0.f);
    a1.y = fmaxf(a1.y + s1.y * inv + b1.y, 0.f);
    a1.z = fmaxf(a1.z + s1.z * inv + b1.z, 0.f);
    a1.w = fmaxf(a1.w + s1.w * inv + b1.w, 0.f);
    if (qw == 0) {
        ((float4*)h)[(size_t)warp * 16 + 2 * li]     = a0;
        ((float4*)h)[(size_t)warp * 16 + 2 * li + 1] = a1;
    }
    // pooling score: tanh(h.p/||p||). Sums are 4x duplicated across quarter-warps:
    // dot_red = 4D, pp_red = 4P -> 4D/(2 sqrt(P)) = 2 D/sqrt(P) -> scale 0.5.
    float4 p0 = ((const float4*)p)[2 * li];
    float4 p1 = ((const float4*)p)[2 * li + 1];
    float dot = a0.x * p0.x + a0.y * p0.y + a0.z * p0.z + a0.w * p0.w
              + a1.x * p1.x + a1.y * p1.y + a1.z * p1.z + a1.w * p1.w;
    float pp  = p0.x * p0.x + p0.y * p0.y + p0.z * p0.z + p0.w * p0.w
              + p1.x * p1.x + p1.y * p1.y + p1.z * p1.z + p1.w * p1.w;
#pragma unroll
    for (int o = 16; o; o >>= 1) {
        dot += __shfl_down_sync(FULLMASK, dot, o);
        pp  += __shfl_down_sync(FULLMASK, pp, o);
    }
    if (lane == 0) score[warp] = tanhf(dot * rsqrtf(pp) * 0.5f);
}

// ---------------- per-graph top-k via bitonic sort (1024 threads) ------------
__global__ __launch_bounds__(1024) void topk_kernel(
    const float* __restrict__ score, int n_per, int k,
    int* __restrict__ perm, float* __restrict__ vals, int* __restrict__ newid) {
    __shared__ unsigned long long keys[2048];
    int b = blockIdx.x;
    int tid = threadIdx.x;
    const float* sc = score + (size_t)b * n_per;
#pragma unroll
    for (int i = tid; i < 2048; i += 1024) {
        unsigned long long key;
        if (i < n_per) {
            unsigned u = __float_as_uint(sc[i]);
            u = (u & 0x80000000u) ? ~u : (u | 0x80000000u);
            key = ((unsigned long long)(~u) << 32) | (unsigned)i;
        } else {
            key = 0xFFFFFFFFFFFFFFFFull;
        }
        keys[i] = key;
    }
    __syncthreads();
    for (int kk = 2; kk <= 2048; kk <<= 1) {
        for (int jj = kk >> 1; jj > 0; jj >>= 1) {
#pragma unroll
            for (int i = tid; i < 2048; i += 1024) {
                int ixj = i ^ jj;
                if (ixj > i) {
                    unsigned long long a = keys[i], c = keys[ixj];
                    bool swap = ((i & kk) == 0) ? (a > c) : (a < c);
                    if (swap) { keys[i] = c; keys[ixj] = a; }
                }
            }
            __syncthreads();
        }
    }
    for (int r = tid; r < k; r += 1024) {
        int idx = (int)(keys[r] & 0xFFFFFFFFull);
        int g_old = b * n_per + idx;
        perm[b * k + r] = g_old;
        vals[b * k + r] = sc[idx];
        if (newid) newid[g_old] = b * k + r;
    }
}

// ---------------- per-graph [max | mean] over gathered+gated rows ------------
__global__ __launch_bounds__(1024) void maxmean_kernel(
    const float* __restrict__ h, const int* __restrict__ perm,
    const float* __restrict__ vals, int k, float* __restrict__ out) {
    __shared__ float smx[1024], ssm[1024];
    int b = blockIdx.x;
    int tid = threadIdx.x;
    int j = tid & 63;
    int rg = tid >> 6;          // 0..15
    float mx = -INFINITY, sum = 0.f;
    for (int r = rg; r < k; r += 16) {
        int idx = perm[b * k + r];
        float v = h[(size_t)idx * 64 + j] * vals[b * k + r];
        mx = fmaxf(mx, v);
        sum += v;
    }
    smx[tid] = mx;
    ssm[tid] = sum;
    __syncthreads();
    for (int s = 8; s >= 1; s >>= 1) {
        if (rg < s) {
            smx[rg * 64 + j] = fmaxf(smx[rg * 64 + j], smx[(rg + s) * 64 + j]);
            ssm[rg * 64 + j] += ssm[(rg + s) * 64 + j];
        }
        __syncthreads();
    }
    if (rg == 0) {
        out[b * 128 + j]      = smx[j];
        out[b * 128 + 64 + j] = ssm[j] / (float)k;
    }
}

// ---------------- MLP head ---------------------------------------------------
__global__ __launch_bounds__(64) void head_kernel(
    const float* __restrict__ x1, const float* __restrict__ x2,
    const float* __restrict__ l1w, const float* __restrict__ l1b,
    const float* __restrict__ l2w, const float* __restrict__ l2b,
    float* __restrict__ out) {
    int b = blockIdx.x;
    int j = threadIdx.x;
    __shared__ float hv[128];
    __shared__ float h1[64];
    hv[j]      = x1[b * 128 + j]      + x2[b * 128 + j];
    hv[j + 64] = x1[b * 128 + 64 + j] + x2[b * 128 + 64 + j];
    __syncthreads();
    float acc = l1b[j];
#pragma unroll 8
    for (int k = 0; k < 128; k++) acc += hv[k] * l1w[k * 64 + j];
    h1[j] = fmaxf(acc, 0.f);
    __syncthreads();
    if (j < NCLS) {
        float o = l2b[j];
#pragma unroll 8
        for (int kk = 0; kk < 64; kk++) o += h1[kk] * l2w[kk * NCLS + j];
        out[b * NCLS + j] = o;
    }
}

// ---------------- host orchestration ----------------------------------------
extern "C" void kernel_launch(void* const* d_in, const int* in_sizes, int n_in,
                              void* d_out, int out_size) {
    const float* x   = (const float*)d_in[0];
    const int* ei    = (const int*)d_in[1];
    const float* W1  = (const float*)d_in[3];
    const float* b1  = (const float*)d_in[4];
    const float* p1  = (const float*)d_in[5];
    const float* W2  = (const float*)d_in[6];
    const float* b2  = (const float*)d_in[7];
    const float* p2  = (const float*)d_in[8];
    const float* l1w = (const float*)d_in[9];
    const float* l1b = (const float*)d_in[10];
    const float* l2w = (const float*)d_in[11];
    const float* l2b = (const float*)d_in[12];
    float* out = (float*)d_out;

    const int* src = ei;
    const int* dst = ei + EDG;

    float *xw, *h, *score, *rdeg, *vals, *x1, *x2;
    int *cnt, *elist, *perm, *newid;
    cudaGetSymbolAddress((void**)&xw,     g_xw);
    cudaGetSymbolAddress((void**)&h,      g_h);
    cudaGetSymbolAddress((void**)&score,  g_score);
    cudaGetSymbolAddress((void**)&rdeg,   g_rdeg);
    cudaGetSymbolAddress((void**)&cnt,    g_cnt);
    cudaGetSymbolAddress((void**)&elist,  g_elist);
    cudaGetSymbolAddress((void**)&perm,   g_perm);
    cudaGetSymbolAddress((void**)&newid,  g_newid);
    cudaGetSymbolAddress((void**)&vals,   g_vals);
    cudaGetSymbolAddress((void**)&x1,     g_x1);
    cudaGetSymbolAddress((void**)&x2,     g_x2);

    const int TB = 256;
    const int EB = (EDG + TB - 1) / TB;

    // ===================== Stage 1 =====================
    fill_i_kernel<<<256, TB>>>(cnt, 0, NTOT);
    place1_kernel<<<EB, TB>>>(src, dst, cnt, elist, EDG);
    rdeg_kernel<<<(NTOT + TB - 1) / TB, TB>>>(cnt, rdeg, NTOT);

    matmul64_kernel<<<NTOT / 64, TB>>>(x, W1, nullptr, nullptr, xw, NTOT);
    conv_kernel<<<(NTOT * 32 + TB - 1) / TB, TB>>>(cnt, elist, rdeg, xw, b1, p1, h, score, NTOT);

    fill_i_kernel<<<256, TB>>>(newid, -1, NTOT);
    topk_kernel<<<BG, 1024>>>(score, NPG, K1, perm, vals, newid);
    maxmean_kernel<<<BG, 1024>>>(h, perm, vals, K1, x1);

    // ===================== Stage 2 =====================
    fill_i_kernel<<<256, TB>>>(cnt, 0, NT1);
    place2_kernel<<<EB, TB>>>(src, dst, newid, cnt, elist, EDG);
    rdeg_kernel<<<(NT1 + TB - 1) / TB, TB>>>(cnt, rdeg, NT1);

    matmul64_kernel<<<NT1 / 64, TB>>>(h, W2, perm, vals, xw, NT1);
    conv_kernel<<<(NT1 * 32 + TB - 1) / TB, TB>>>(cnt, elist, rdeg, xw, b2, p2, h, score, NT1);

    topk_kernel<<<BG, 1024>>>(score, K1, K2, perm, vals, (int*)nullptr);
    maxmean_kernel<<<BG, 1024>>>(h, perm, vals, K2, x2);

    // ===================== Head =====================
    head_kernel<<<BG, 64>>>(x1, x2, l1w, l1b, l2w, l2b, out);
}

// round 5
// speedup vs baseline: 1.4986x; 1.4986x over previous
#include <cuda_runtime.h>
#include <cuda_bf16.h>
#include <math.h>

#define BG   64
#define NPG  2048
#define EPG  32768
#define NTOT (BG * NPG)         // 131072
#define EDG  (BG * EPG)         // 2097152
#define K1   1639
#define NT1  (BG * K1)          // 104896
#define K2   1312
#define NT2  (BG * K2)          // 83968
#define DIM  64
#define NCLS 6
#define CAP  64                 // fixed CSR bucket capacity (P(deg>=64) ~ 1e-20)
#define FULLMASK 0xFFFFFFFFu

// ---------------- scratch ----------------------------------------------------
__device__ float g_xw[NTOT * DIM];       // x@W (stage1), gathered-xp@W2 (stage2)
__device__ float g_h[NTOT * DIM];        // conv output (relu'd)
__device__ float g_score[NTOT];
__device__ float g_rdeg[NTOT];           // rsqrt(deg incl self-loop)
__device__ int   g_cnt[NTOT];            // in-degree (excl self-loop)
__device__ int   g_elist[NTOT * CAP];    // fixed-stride CSR: src per dst-slot
__device__ int   g_perm[NT1];
__device__ float g_vals[NT1];
__device__ int   g_newid[NTOT];
__device__ float g_x1[BG * 2 * DIM];
__device__ float g_x2[BG * 2 * DIM];

// ---------------- utility ----------------------------------------------------
__global__ void fill_i_kernel(int* p, int v, int n) {
    int t = blockIdx.x * blockDim.x + threadIdx.x;
    int stride = gridDim.x * blockDim.x;
    for (; t < n; t += stride) p[t] = v;
}

// fused count + place (stage 1: all edges valid)
__global__ void place1_kernel(const int* __restrict__ src, const int* __restrict__ dst,
                              int* __restrict__ cnt, int* __restrict__ elist, int nedges) {
    int t = blockIdx.x * blockDim.x + threadIdx.x;
    if (t >= nedges) return;
    int d = dst[t];
    int slot = atomicAdd(&cnt[d], 1);
    elist[d * CAP + slot] = src[t];
}

// fused remap + count + place (stage 2)
__global__ void place2_kernel(const int* __restrict__ src, const int* __restrict__ dst,
                              const int* __restrict__ newid,
                              int* __restrict__ cnt, int* __restrict__ elist, int nedges) {
    int t = blockIdx.x * blockDim.x + threadIdx.x;
    if (t >= nedges) return;
    int s2 = newid[src[t]];
    int d2 = newid[dst[t]];
    if (s2 < 0 || d2 < 0) return;
    int slot = atomicAdd(&cnt[d2], 1);
    elist[d2 * CAP + slot] = s2;
}

__global__ void rdeg_kernel(const int* __restrict__ cnt, float* __restrict__ rdeg, int n) {
    int i = blockIdx.x * blockDim.x + threadIdx.x;
    if (i < n) rdeg[i] = rsqrtf((float)(cnt[i] + 1));
}

// ---------------- GEMM: C[n x 64] = gather(A)[n x 64] @ W[64 x 64] ----------
// 128-row tile per block; thread = 8 rows x 4 cols (cols tx, tx+16, tx+32, tx+48).
// W repacked in smem as Ws[k4][j][4] (16B chunk = 4 k-values for col j) so the
// 16 lanes of each LDS128 phase hit consecutive chunks -> conflict-free.
// A reads are 16-lane broadcasts. LDS bytes/FMA = 1.5 -> FFMA-pipe bound.
// If perm != nullptr, row i of A is A[perm[i]] * vals[i] (fused TopK gather+gate).
__global__ __launch_bounds__(256) void matmul64_kernel(
    const float* __restrict__ A, const float* __restrict__ W,
    const int* __restrict__ perm, const float* __restrict__ vals,
    float* __restrict__ C, int nrows) {
    __shared__ float Ws[16][64][4];   // [k4][col][k-in-group]
    __shared__ float As[128][64];
    int tid = threadIdx.x;
    // repack W: W[k][j] row-major -> Ws[k>>2][j][k&3]
    for (int i = tid; i < 4096; i += 256) {
        int k = i >> 6, j = i & 63;
        Ws[k >> 2][j][k & 3] = W[i];
    }
    int row0 = blockIdx.x * 128;
    {
        float4* s4 = (float4*)&As[0][0];
        for (int i = tid; i < 2048; i += 256) {
            int grow = row0 + (i >> 4);
            float4 v = make_float4(0.f, 0.f, 0.f, 0.f);
            if (grow < nrows) {
                int arow = perm ? perm[grow] : grow;
                float sc = perm ? vals[grow] : 1.0f;
                v = ((const float4*)(A + (size_t)arow * 64))[i & 15];
                v.x *= sc; v.y *= sc; v.z *= sc; v.w *= sc;
            }
            s4[i] = v;
        }
    }
    __syncthreads();
    int tx = tid & 15;    // col base
    int ty = tid >> 4;    // row group: rows ty*8 .. ty*8+7
    float acc[8][4] = {};
#pragma unroll
    for (int k4 = 0; k4 < 16; k4++) {
        float4 w[4];
#pragma unroll
        for (int c = 0; c < 4; c++)
            w[c] = *(const float4*)&Ws[k4][tx + 16 * c][0];
#pragma unroll
        for (int r = 0; r < 8; r++) {
            float4 a = *(const float4*)&As[ty * 8 + r][k4 * 4];
#pragma unroll
            for (int c = 0; c < 4; c++)
                acc[r][c] += a.x * w[c].x + a.y * w[c].y + a.z * w[c].z + a.w * w[c].w;
        }
    }
#pragma unroll
    for (int r = 0; r < 8; r++) {
        int row = row0 + ty * 8 + r;
        if (row < nrows) {
#pragma unroll
            for (int c = 0; c < 4; c++)
                C[(size_t)row * 64 + tx + 16 * c] = acc[r][c];
        }
    }
}

// ---------------- fused CSR-gather conv + epilogue + score -------------------
// One warp per dst node; the two half-warps each process alternate edges with
// float4 lanes (16 lanes x 16B = full 64-float row), combined at the end.
__global__ __launch_bounds__(256) void conv_kernel(
    const int* __restrict__ cnt, const int* __restrict__ elist,
    const float* __restrict__ rdeg, const float* __restrict__ xw,
    const float* __restrict__ bias, const float* __restrict__ p,
    float* __restrict__ h, float* __restrict__ score, int n) {
    int warp = (blockIdx.x * blockDim.x + threadIdx.x) >> 5;
    int lane = threadIdx.x & 31;
    if (warp >= n) return;
    int li   = lane & 15;
    int half = lane >> 4;
    const float4* xw4 = (const float4*)xw;
    float rd = rdeg[warp];
    int m = cnt[warp];
    const int* el = elist + (size_t)warp * CAP;
    float4 acc = make_float4(0.f, 0.f, 0.f, 0.f);
#pragma unroll 2
    for (int e = half; e < m; e += 2) {
        int s = el[e];
        float nr = rdeg[s] * rd;
        float4 v = xw4[(size_t)s * 16 + li];
        acc.x += nr * v.x; acc.y += nr * v.y;
        acc.z += nr * v.z; acc.w += nr * v.w;
    }
    // combine halves (both halves end up with full sums)
    acc.x += __shfl_xor_sync(FULLMASK, acc.x, 16);
    acc.y += __shfl_xor_sync(FULLMASK, acc.y, 16);
    acc.z += __shfl_xor_sync(FULLMASK, acc.z, 16);
    acc.w += __shfl_xor_sync(FULLMASK, acc.w, 16);
    // self-loop (coef 1/deg = rd^2) + bias + relu
    float4 vs = xw4[(size_t)warp * 16 + li];
    float4 b4 = ((const float4*)bias)[li];
    float inv = rd * rd;
    acc.x = fmaxf(acc.x + vs.x * inv + b4.x, 0.f);
    acc.y = fmaxf(acc.y + vs.y * inv + b4.y, 0.f);
    acc.z = fmaxf(acc.z + vs.z * inv + b4.z, 0.f);
    acc.w = fmaxf(acc.w + vs.w * inv + b4.w, 0.f);
    if (half == 0) ((float4*)h)[(size_t)warp * 16 + li] = acc;
    // pooling score: tanh(h.p / ||p||). Both halves duplicate -> full-warp sums
    // are 2x; the sqrt(2) factor corrects dot/sqrt(pp).
    float4 p4 = ((const float4*)p)[li];
    float dot = acc.x * p4.x + acc.y * p4.y + acc.z * p4.z + acc.w * p4.w;
    float pp  = p4.x * p4.x + p4.y * p4.y + p4.z * p4.z + p4.w * p4.w;
#pragma unroll
    for (int o = 16; o; o >>= 1) {
        dot += __shfl_down_sync(FULLMASK, dot, o);
        pp  += __shfl_down_sync(FULLMASK, pp, o);
    }
    if (lane == 0) score[warp] = tanhf(dot * rsqrtf(pp) * 0.7071067811865476f);
}

// ---------------- per-graph top-k via bitonic sort (1024 threads) ------------
__global__ __launch_bounds__(1024) void topk_kernel(
    const float* __restrict__ score, int n_per, int k,
    int* __restrict__ perm, float* __restrict__ vals, int* __restrict__ newid) {
    __shared__ unsigned long long keys[2048];
    int b = blockIdx.x;
    int tid = threadIdx.x;
    const float* sc = score + (size_t)b * n_per;
#pragma unroll
    for (int i = tid; i < 2048; i += 1024) {
        unsigned long long key;
        if (i < n_per) {
            unsigned u = __float_as_uint(sc[i]);
            u = (u & 0x80000000u) ? ~u : (u | 0x80000000u);
            key = ((unsigned long long)(~u) << 32) | (unsigned)i;
        } else {
            key = 0xFFFFFFFFFFFFFFFFull;
        }
        keys[i] = key;
    }
    __syncthreads();
    for (int kk = 2; kk <= 2048; kk <<= 1) {
        for (int jj = kk >> 1; jj > 0; jj >>= 1) {
#pragma unroll
            for (int i = tid; i < 2048; i += 1024) {
                int ixj = i ^ jj;
                if (ixj > i) {
                    unsigned long long a = keys[i], c = keys[ixj];
                    bool swap = ((i & kk) == 0) ? (a > c) : (a < c);
                    if (swap) { keys[i] = c; keys[ixj] = a; }
                }
            }
            __syncthreads();
        }
    }
    for (int r = tid; r < k; r += 1024) {
        int idx = (int)(keys[r] & 0xFFFFFFFFull);
        int g_old = b * n_per + idx;
        perm[b * k + r] = g_old;
        vals[b * k + r] = sc[idx];
        if (newid) newid[g_old] = b * k + r;
    }
}

// ---------------- per-graph [max | mean] over gathered+gated rows ------------
__global__ __launch_bounds__(1024) void maxmean_kernel(
    const float* __restrict__ h, const int* __restrict__ perm,
    const float* __restrict__ vals, int k, float* __restrict__ out) {
    __shared__ float smx[1024], ssm[1024];
    int b = blockIdx.x;
    int tid = threadIdx.x;
    int j = tid & 63;
    int rg = tid >> 6;          // 0..15
    float mx = -INFINITY, sum = 0.f;
    for (int r = rg; r < k; r += 16) {
        int idx = perm[b * k + r];
        float v = h[(size_t)idx * 64 + j] * vals[b * k + r];
        mx = fmaxf(mx, v);
        sum += v;
    }
    smx[tid] = mx;
    ssm[tid] = sum;
    __syncthreads();
    for (int s = 8; s >= 1; s >>= 1) {
        if (rg < s) {
            smx[rg * 64 + j] = fmaxf(smx[rg * 64 + j], smx[(rg + s) * 64 + j]);
            ssm[rg * 64 + j] += ssm[(rg + s) * 64 + j];
        }
        __syncthreads();
    }
    if (rg == 0) {
        out[b * 128 + j]      = smx[j];
        out[b * 128 + 64 + j] = ssm[j] / (float)k;
    }
}

// ---------------- MLP head ---------------------------------------------------
__global__ __launch_bounds__(64) void head_kernel(
    const float* __restrict__ x1, const float* __restrict__ x2,
    const float* __restrict__ l1w, const float* __restrict__ l1b,
    const float* __restrict__ l2w, const float* __restrict__ l2b,
    float* __restrict__ out) {
    int b = blockIdx.x;
    int j = threadIdx.x;
    __shared__ float hv[128];
    __shared__ float h1[64];
    hv[j]      = x1[b * 128 + j]      + x2[b * 128 + j];
    hv[j + 64] = x1[b * 128 + 64 + j] + x2[b * 128 + 64 + j];
    __syncthreads();
    float acc = l1b[j];
#pragma unroll 8
    for (int k = 0; k < 128; k++) acc += hv[k] * l1w[k * 64 + j];
    h1[j] = fmaxf(acc, 0.f);
    __syncthreads();
    if (j < NCLS) {
        float o = l2b[j];
#pragma unroll 8
        for (int kk = 0; kk < 64; kk++) o += h1[kk] * l2w[kk * NCLS + j];
        out[b * NCLS + j] = o;
    }
}

// ---------------- host orchestration ----------------------------------------
extern "C" void kernel_launch(void* const* d_in, const int* in_sizes, int n_in,
                              void* d_out, int out_size) {
    const float* x   = (const float*)d_in[0];
    const int* ei    = (const int*)d_in[1];
    const float* W1  = (const float*)d_in[3];
    const float* b1  = (const float*)d_in[4];
    const float* p1  = (const float*)d_in[5];
    const float* W2  = (const float*)d_in[6];
    const float* b2  = (const float*)d_in[7];
    const float* p2  = (const float*)d_in[8];
    const float* l1w = (const float*)d_in[9];
    const float* l1b = (const float*)d_in[10];
    const float* l2w = (const float*)d_in[11];
    const float* l2b = (const float*)d_in[12];
    float* out = (float*)d_out;

    const int* src = ei;
    const int* dst = ei + EDG;

    float *xw, *h, *score, *rdeg, *vals, *x1, *x2;
    int *cnt, *elist, *perm, *newid;
    cudaGetSymbolAddress((void**)&xw,     g_xw);
    cudaGetSymbolAddress((void**)&h,      g_h);
    cudaGetSymbolAddress((void**)&score,  g_score);
    cudaGetSymbolAddress((void**)&rdeg,   g_rdeg);
    cudaGetSymbolAddress((void**)&cnt,    g_cnt);
    cudaGetSymbolAddress((void**)&elist,  g_elist);
    cudaGetSymbolAddress((void**)&perm,   g_perm);
    cudaGetSymbolAddress((void**)&newid,  g_newid);
    cudaGetSymbolAddress((void**)&vals,   g_vals);
    cudaGetSymbolAddress((void**)&x1,     g_x1);
    cudaGetSymbolAddress((void**)&x2,     g_x2);

    const int TB = 256;
    const int EB = (EDG + TB - 1) / TB;

    // ===================== Stage 1 =====================
    fill_i_kernel<<<256, TB>>>(cnt, 0, NTOT);
    place1_kernel<<<EB, TB>>>(src, dst, cnt, elist, EDG);
    rdeg_kernel<<<(NTOT + TB - 1) / TB, TB>>>(cnt, rdeg, NTOT);

    matmul64_kernel<<<(NTOT + 127) / 128, TB>>>(x, W1, nullptr, nullptr, xw, NTOT);
    conv_kernel<<<(NTOT * 32 + TB - 1) / TB, TB>>>(cnt, elist, rdeg, xw, b1, p1, h, score, NTOT);

    fill_i_kernel<<<256, TB>>>(newid, -1, NTOT);
    topk_kernel<<<BG, 1024>>>(score, NPG, K1, perm, vals, newid);
    maxmean_kernel<<<BG, 1024>>>(h, perm, vals, K1, x1);

    // ===================== Stage 2 =====================
    fill_i_kernel<<<256, TB>>>(cnt, 0, NT1);
    place2_kernel<<<EB, TB>>>(src, dst, newid, cnt, elist, EDG);
    rdeg_kernel<<<(NT1 + TB - 1) / TB, TB>>>(cnt, rdeg, NT1);

    matmul64_kernel<<<(NT1 + 127) / 128, TB>>>(h, W2, perm, vals, xw, NT1);
    conv_kernel<<<(NT1 * 32 + TB - 1) / TB, TB>>>(cnt, elist, rdeg, xw, b2, p2, h, score, NT1);

    topk_kernel<<<BG, 1024>>>(score, K1, K2, perm, vals, (int*)nullptr);
    maxmean_kernel<<<BG, 1024>>>(h, perm, vals, K2, x2);

    // ===================== Head =====================
    head_kernel<<<BG, 64>>>(x1, x2, l1w, l1b, l2w, l2b, out);
}

// round 6
// speedup vs baseline: 1.6280x; 1.0864x over previous
#include <cuda_runtime.h>
#include <cuda_bf16.h>
#include <math.h>

#define BG   64
#define NPG  2048
#define EPG  32768
#define NTOT (BG * NPG)         // 131072
#define EDG  (BG * EPG)         // 2097152
#define K1   1639
#define NT1  (BG * K1)          // 104896 (divisible by 64)
#define K2   1312
#define NT2  (BG * K2)          // 83968
#define DIM  64
#define NCLS 6
#define CAP  64                 // fixed CSR bucket capacity (P(deg>=64) ~ 1e-20)
#define FULLMASK 0xFFFFFFFFu

// ---------------- scratch ----------------------------------------------------
__device__ float g_xw[NTOT * DIM];       // x@W (stage1), gathered-xp@W2 (stage2)
__device__ float g_h[NTOT * DIM];        // conv output (relu'd)
__device__ float g_score[NTOT];
__device__ float g_rdeg[NTOT];           // rsqrt(deg incl self-loop)
__device__ int   g_cnt[NTOT];            // in-degree (excl self-loop)
__device__ int   g_elist[NTOT * CAP];    // fixed-stride CSR: src per dst-slot
__device__ int   g_perm[NT1];
__device__ float g_vals[NT1];
__device__ int   g_newid[NTOT];
__device__ float g_x1[BG * 2 * DIM];
__device__ float g_x2[BG * 2 * DIM];

// ---------------- stage-1 init: cnt=0, newid=-1 ------------------------------
__global__ void init1_kernel(int* __restrict__ cnt, int* __restrict__ newid, int n) {
    int t = blockIdx.x * blockDim.x + threadIdx.x;
    int stride = gridDim.x * blockDim.x;
    for (; t < n; t += stride) { cnt[t] = 0; newid[t] = -1; }
}

// fused count + place (stage 1: all edges valid)
__global__ void place1_kernel(const int* __restrict__ src, const int* __restrict__ dst,
                              int* __restrict__ cnt, int* __restrict__ elist, int nedges) {
    int t = blockIdx.x * blockDim.x + threadIdx.x;
    if (t >= nedges) return;
    int d = dst[t];
    int slot = atomicAdd(&cnt[d], 1);
    elist[d * CAP + slot] = src[t];
}

// fused remap + count + place (stage 2)
__global__ void place2_kernel(const int* __restrict__ src, const int* __restrict__ dst,
                              const int* __restrict__ newid,
                              int* __restrict__ cnt, int* __restrict__ elist, int nedges) {
    int t = blockIdx.x * blockDim.x + threadIdx.x;
    if (t >= nedges) return;
    int s2 = newid[src[t]];
    int d2 = newid[dst[t]];
    if (s2 < 0 || d2 < 0) return;
    int slot = atomicAdd(&cnt[d2], 1);
    elist[d2 * CAP + slot] = s2;
}

// ---------------- GEMM: C[n x 64] = gather(A)[n x 64] @ W[64 x 64] ----------
// 64-row tile; thread = 4 rows x 4 cols (cols tx, tx+16, tx+32, tx+48).
// W repacked as Ws[k4][j][4] -> conflict-free LDS128; A reads are broadcasts.
// Also fuses the rdeg pass: rdeg[i] = rsqrt(cnt[i]+1) (grid covers all nodes).
// If perm != nullptr, row i of A is A[perm[i]] * vals[i] (fused TopK gather+gate).
__global__ __launch_bounds__(256, 4) void matmul64_kernel(
    const float* __restrict__ A, const float* __restrict__ W,
    const int* __restrict__ perm, const float* __restrict__ vals,
    float* __restrict__ C, int nrows,
    const int* __restrict__ cnt, float* __restrict__ rdeg) {
    __shared__ float Ws[16][64][4];   // [k4][col][k-in-group]
    __shared__ float As[64][64];
    int tid = threadIdx.x;
    // fused rdeg pass (cnt is final here: GEMM launches after place)
    int gi = blockIdx.x * 256 + tid;
    if (gi < nrows) rdeg[gi] = rsqrtf((float)(cnt[gi] + 1));
    // repack W: W[k][j] row-major -> Ws[k>>2][j][k&3]
    for (int i = tid; i < 4096; i += 256) {
        int k = i >> 6, j = i & 63;
        Ws[k >> 2][j][k & 3] = W[i];
    }
    int row0 = blockIdx.x * 64;
    {
        float4* s4 = (float4*)&As[0][0];
        for (int i = tid; i < 1024; i += 256) {
            int grow = row0 + (i >> 4);       // grow < nrows (nrows % 64 == 0)
            int arow = perm ? perm[grow] : grow;
            float sc = perm ? vals[grow] : 1.0f;
            float4 v = ((const float4*)(A + (size_t)arow * 64))[i & 15];
            v.x *= sc; v.y *= sc; v.z *= sc; v.w *= sc;
            s4[i] = v;
        }
    }
    __syncthreads();
    int tx = tid & 15;    // col base
    int ty = tid >> 4;    // rows ty*4 .. ty*4+3
    float acc[4][4] = {};
#pragma unroll
    for (int k4 = 0; k4 < 16; k4++) {
        float4 w[4];
#pragma unroll
        for (int c = 0; c < 4; c++)
            w[c] = *(const float4*)&Ws[k4][tx + 16 * c][0];
#pragma unroll
        for (int r = 0; r < 4; r++) {
            float4 a = *(const float4*)&As[ty * 4 + r][k4 * 4];
#pragma unroll
            for (int c = 0; c < 4; c++)
                acc[r][c] += a.x * w[c].x + a.y * w[c].y + a.z * w[c].z + a.w * w[c].w;
        }
    }
#pragma unroll
    for (int r = 0; r < 4; r++) {
        int row = row0 + ty * 4 + r;
#pragma unroll
        for (int c = 0; c < 4; c++)
            C[(size_t)row * 64 + tx + 16 * c] = acc[r][c];
    }
}

// ---------------- fused CSR-gather conv + epilogue + score -------------------
// One warp per dst node; the two half-warps each process alternate edges with
// float4 lanes (16 lanes x 16B = full 64-float row), combined at the end.
__global__ __launch_bounds__(256) void conv_kernel(
    const int* __restrict__ cnt, const int* __restrict__ elist,
    const float* __restrict__ rdeg, const float* __restrict__ xw,
    const float* __restrict__ bias, const float* __restrict__ p,
    float* __restrict__ h, float* __restrict__ score, int n) {
    int warp = (blockIdx.x * blockDim.x + threadIdx.x) >> 5;
    int lane = threadIdx.x & 31;
    if (warp >= n) return;
    int li   = lane & 15;
    int half = lane >> 4;
    const float4* xw4 = (const float4*)xw;
    float rd = rdeg[warp];
    int m = cnt[warp];
    const int* el = elist + (size_t)warp * CAP;
    float4 acc = make_float4(0.f, 0.f, 0.f, 0.f);
#pragma unroll 2
    for (int e = half; e < m; e += 2) {
        int s = el[e];
        float nr = rdeg[s] * rd;
        float4 v = xw4[(size_t)s * 16 + li];
        acc.x += nr * v.x; acc.y += nr * v.y;
        acc.z += nr * v.z; acc.w += nr * v.w;
    }
    // combine halves (both halves end up with full sums)
    acc.x += __shfl_xor_sync(FULLMASK, acc.x, 16);
    acc.y += __shfl_xor_sync(FULLMASK, acc.y, 16);
    acc.z += __shfl_xor_sync(FULLMASK, acc.z, 16);
    acc.w += __shfl_xor_sync(FULLMASK, acc.w, 16);
    // self-loop (coef 1/deg = rd^2) + bias + relu
    float4 vs = xw4[(size_t)warp * 16 + li];
    float4 b4 = ((const float4*)bias)[li];
    float inv = rd * rd;
    acc.x = fmaxf(acc.x + vs.x * inv + b4.x, 0.f);
    acc.y = fmaxf(acc.y + vs.y * inv + b4.y, 0.f);
    acc.z = fmaxf(acc.z + vs.z * inv + b4.z, 0.f);
    acc.w = fmaxf(acc.w + vs.w * inv + b4.w, 0.f);
    if (half == 0) ((float4*)h)[(size_t)warp * 16 + li] = acc;
    // pooling score: tanh(h.p / ||p||). Both halves duplicate -> full-warp sums
    // are 2x; the sqrt(2) factor corrects dot/sqrt(pp).
    float4 p4 = ((const float4*)p)[li];
    float dot = acc.x * p4.x + acc.y * p4.y + acc.z * p4.z + acc.w * p4.w;
    float pp  = p4.x * p4.x + p4.y * p4.y + p4.z * p4.z + p4.w * p4.w;
#pragma unroll
    for (int o = 16; o; o >>= 1) {
        dot += __shfl_down_sync(FULLMASK, dot, o);
        pp  += __shfl_down_sync(FULLMASK, pp, o);
    }
    if (lane == 0) score[warp] = tanhf(dot * rsqrtf(pp) * 0.7071067811865476f);
}

// ---------------- per-graph top-k via bitonic sort (1024 threads) ------------
// Also zeroes cnt[b*k + r] for the kept nodes (= stage-2 cnt init).
__global__ __launch_bounds__(1024) void topk_kernel(
    const float* __restrict__ score, int n_per, int k,
    int* __restrict__ perm, float* __restrict__ vals, int* __restrict__ newid,
    int* __restrict__ cnt_zero) {
    __shared__ unsigned long long keys[2048];
    int b = blockIdx.x;
    int tid = threadIdx.x;
    const float* sc = score + (size_t)b * n_per;
#pragma unroll
    for (int i = tid; i < 2048; i += 1024) {
        unsigned long long key;
        if (i < n_per) {
            unsigned u = __float_as_uint(sc[i]);
            u = (u & 0x80000000u) ? ~u : (u | 0x80000000u);
            key = ((unsigned long long)(~u) << 32) | (unsigned)i;
        } else {
            key = 0xFFFFFFFFFFFFFFFFull;
        }
        keys[i] = key;
    }
    __syncthreads();
    for (int kk = 2; kk <= 2048; kk <<= 1) {
        for (int jj = kk >> 1; jj > 0; jj >>= 1) {
#pragma unroll
            for (int i = tid; i < 2048; i += 1024) {
                int ixj = i ^ jj;
                if (ixj > i) {
                    unsigned long long a = keys[i], c = keys[ixj];
                    bool swap = ((i & kk) == 0) ? (a > c) : (a < c);
                    if (swap) { keys[i] = c; keys[ixj] = a; }
                }
            }
            __syncthreads();
        }
    }
    for (int r = tid; r < k; r += 1024) {
        int idx = (int)(keys[r] & 0xFFFFFFFFull);
        int g_old = b * n_per + idx;
        perm[b * k + r] = g_old;
        vals[b * k + r] = sc[idx];
        if (newid) newid[g_old] = b * k + r;
        if (cnt_zero) cnt_zero[b * k + r] = 0;
    }
}

// ---------------- per-graph [max | mean] over gathered+gated rows ------------
__global__ __launch_bounds__(1024) void maxmean_kernel(
    const float* __restrict__ h, const int* __restrict__ perm,
    const float* __restrict__ vals, int k, float* __restrict__ out) {
    __shared__ float smx[1024], ssm[1024];
    int b = blockIdx.x;
    int tid = threadIdx.x;
    int j = tid & 63;
    int rg = tid >> 6;          // 0..15
    float mx = -INFINITY, sum = 0.f;
    for (int r = rg; r < k; r += 16) {
        int idx = perm[b * k + r];
        float v = h[(size_t)idx * 64 + j] * vals[b * k + r];
        mx = fmaxf(mx, v);
        sum += v;
    }
    smx[tid] = mx;
    ssm[tid] = sum;
    __syncthreads();
    for (int s = 8; s >= 1; s >>= 1) {
        if (rg < s) {
            smx[rg * 64 + j] = fmaxf(smx[rg * 64 + j], smx[(rg + s) * 64 + j]);
            ssm[rg * 64 + j] += ssm[(rg + s) * 64 + j];
        }
        __syncthreads();
    }
    if (rg == 0) {
        out[b * 128 + j]      = smx[j];
        out[b * 128 + 64 + j] = ssm[j] / (float)k;
    }
}

// ---------------- MLP head ---------------------------------------------------
__global__ __launch_bounds__(64) void head_kernel(
    const float* __restrict__ x1, const float* __restrict__ x2,
    const float* __restrict__ l1w, const float* __restrict__ l1b,
    const float* __restrict__ l2w, const float* __restrict__ l2b,
    float* __restrict__ out) {
    int b = blockIdx.x;
    int j = threadIdx.x;
    __shared__ float hv[128];
    __shared__ float h1[64];
    hv[j]      = x1[b * 128 + j]      + x2[b * 128 + j];
    hv[j + 64] = x1[b * 128 + 64 + j] + x2[b * 128 + 64 + j];
    __syncthreads();
    float acc = l1b[j];
#pragma unroll 8
    for (int k = 0; k < 128; k++) acc += hv[k] * l1w[k * 64 + j];
    h1[j] = fmaxf(acc, 0.f);
    __syncthreads();
    if (j < NCLS) {
        float o = l2b[j];
#pragma unroll 8
        for (int kk = 0; kk < 64; kk++) o += h1[kk] * l2w[kk * NCLS + j];
        out[b * NCLS + j] = o;
    }
}

// ---------------- host orchestration ----------------------------------------
extern "C" void kernel_launch(void* const* d_in, const int* in_sizes, int n_in,
                              void* d_out, int out_size) {
    const float* x   = (const float*)d_in[0];
    const int* ei    = (const int*)d_in[1];
    const float* W1  = (const float*)d_in[3];
    const float* b1  = (const float*)d_in[4];
    const float* p1  = (const float*)d_in[5];
    const float* W2  = (const float*)d_in[6];
    const float* b2  = (const float*)d_in[7];
    const float* p2  = (const float*)d_in[8];
    const float* l1w = (const float*)d_in[9];
    const float* l1b = (const float*)d_in[10];
    const float* l2w = (const float*)d_in[11];
    const float* l2b = (const float*)d_in[12];
    float* out = (float*)d_out;

    const int* src = ei;
    const int* dst = ei + EDG;

    float *xw, *h, *score, *rdeg, *vals, *x1, *x2;
    int *cnt, *elist, *perm, *newid;
    cudaGetSymbolAddress((void**)&xw,     g_xw);
    cudaGetSymbolAddress((void**)&h,      g_h);
    cudaGetSymbolAddress((void**)&score,  g_score);
    cudaGetSymbolAddress((void**)&rdeg,   g_rdeg);
    cudaGetSymbolAddress((void**)&cnt,    g_cnt);
    cudaGetSymbolAddress((void**)&elist,  g_elist);
    cudaGetSymbolAddress((void**)&perm,   g_perm);
    cudaGetSymbolAddress((void**)&newid,  g_newid);
    cudaGetSymbolAddress((void**)&vals,   g_vals);
    cudaGetSymbolAddress((void**)&x1,     g_x1);
    cudaGetSymbolAddress((void**)&x2,     g_x2);

    const int TB = 256;
    const int EB = (EDG + TB - 1) / TB;

    // ===================== Stage 1 =====================
    init1_kernel<<<256, TB>>>(cnt, newid, NTOT);
    place1_kernel<<<EB, TB>>>(src, dst, cnt, elist, EDG);

    matmul64_kernel<<<NTOT / 64, TB>>>(x, W1, nullptr, nullptr, xw, NTOT, cnt, rdeg);
    conv_kernel<<<(NTOT * 32 + TB - 1) / TB, TB>>>(cnt, elist, rdeg, xw, b1, p1, h, score, NTOT);

    topk_kernel<<<BG, 1024>>>(score, NPG, K1, perm, vals, newid, cnt);  // zeroes cnt for stage 2
    maxmean_kernel<<<BG, 1024>>>(h, perm, vals, K1, x1);

    // ===================== Stage 2 =====================
    place2_kernel<<<EB, TB>>>(src, dst, newid, cnt, elist, EDG);

    matmul64_kernel<<<NT1 / 64, TB>>>(h, W2, perm, vals, xw, NT1, cnt, rdeg);
    conv_kernel<<<(NT1 * 32 + TB - 1) / TB, TB>>>(cnt, elist, rdeg, xw, b2, p2, h, score, NT1);

    topk_kernel<<<BG, 1024>>>(score, K1, K2, perm, vals, (int*)nullptr, (int*)nullptr);
    maxmean_kernel<<<BG, 1024>>>(h, perm, vals, K2, x2);

    // ===================== Head =====================
    head_kernel<<<BG, 64>>>(x1, x2, l1w, l1b, l2w, l2b, out);
}